// round 17
// baseline (speedup 1.0000x reference)
#include <cuda_runtime.h>
#include <cuda_fp16.h>
#include <cstdint>

#define N_NODES 10000
#define N_EDGES 50000
#define IN_F    1433
#define OUT_F   256

#define K_PAD   1440           // K padded to multiple of 32
#define HSLOTS  720            // K_PAD/2 half2 slots per row
#define BK      32
#define N_KT    (K_PAD / BK)   // 45
#define M_PADR  10112          // 79 * 128
#define CAP     64             // per-node bucket capacity (max degree ~18)

#define FEAT_F4_TOTAL  ((N_NODES * IN_F) / 4)     // 3,582,500 (divides exactly)

// fused prep grid split: feat convert (flat f4) | W transpose | edge-bucket fill
#define PREP_FEAT_BLOCKS  3500
#define PREP_W_BLOCKS     (45 * 8)
#define PREP_FILL_BLOCKS  196
#define PREP_GRID         (PREP_FEAT_BLOCKS + PREP_W_BLOCKS + PREP_FILL_BLOCKS)

// -------- scratch (device globals; zero-initialized, no allocations) --------
__device__ __align__(16) __half g_feat16[(size_t)N_NODES * K_PAD];  // tail cols zero (static init)
__device__ __align__(16) __half g_A[(size_t)M_PADR * K_PAD];
__device__ __align__(16) __half g_Wt[(size_t)OUT_F * K_PAD];
__device__ int g_cnt[N_NODES];     // zero-init; gather resets after use
__device__ int g_srcs[(size_t)N_NODES * CAP];

// ======================= helpers =======================
__device__ __forceinline__ uint32_t smem_u32(const void* p) {
    uint32_t a;
    asm("{ .reg .u64 t; cvta.to.shared.u64 t, %1; cvt.u32.u64 %0, t; }" : "=r"(a) : "l"(p));
    return a;
}
__device__ __forceinline__ void ldmx4(uint32_t* r, uint32_t addr) {
    asm volatile("ldmatrix.sync.aligned.m8n8.x4.shared.b16 {%0,%1,%2,%3}, [%4];"
                 : "=r"(r[0]), "=r"(r[1]), "=r"(r[2]), "=r"(r[3]) : "r"(addr));
}
__device__ __forceinline__ void mma_f16(float* d, const uint32_t* a, const uint32_t* b) {
    asm volatile(
        "mma.sync.aligned.m16n8k16.row.col.f32.f16.f16.f32 "
        "{%0,%1,%2,%3}, {%4,%5,%6,%7}, {%8,%9}, {%0,%1,%2,%3};"
        : "+f"(d[0]), "+f"(d[1]), "+f"(d[2]), "+f"(d[3])
        : "r"(a[0]), "r"(a[1]), "r"(a[2]), "r"(a[3]), "r"(b[0]), "r"(b[1]));
}
__device__ __forceinline__ void cp16(uint32_t dst, const void* src) {
    asm volatile("cp.async.cg.shared.global [%0], [%1], 16;" :: "r"(dst), "l"(src));
}
__device__ __forceinline__ void cp_commit() {
    asm volatile("cp.async.commit_group;" ::: "memory");
}
template <int N>
__device__ __forceinline__ void cp_wait() {
    asm volatile("cp.async.wait_group %0;" :: "n"(N) : "memory");
}

// ======================= edge decode =======================
__device__ __forceinline__ void read_edge(const void* edges, int e, int is64,
                                          int& dst, int& src) {
    if (is64) {
        const long long* e64 = (const long long*)edges;
        dst = (int)e64[2 * (size_t)e];
        src = (int)e64[2 * (size_t)e + 1];
    } else {
        const int* e32 = (const int*)edges;
        dst = e32[2 * e];
        src = e32[2 * e + 1];
    }
}

// -------- launch 1: fused prep (feat->fp16 flat f4 | W->fp16^T | bucket fill) --------
__global__ __launch_bounds__(256)
void prep_kernel(const float* __restrict__ feat,
                 const float* __restrict__ W,
                 const void* __restrict__ edges) {
    int b = blockIdx.x;
    int tid = threadIdx.x;

    if (b < PREP_FEAT_BLOCKS) {
        // flat float4 conversion; feat base is 16B-aligned, total f4 count exact
        int gid = b * 256 + tid;
        const float4* __restrict__ f4 = (const float4*)feat;
        for (int i = gid; i < FEAT_F4_TOTAL; i += PREP_FEAT_BLOCKS * 256) {
            float4 v = __ldg(f4 + i);
            int e0 = i * 4;
            // elements e0..e0+3 -> (r, c) with padded dst row stride K_PAD
            #pragma unroll
            for (int k = 0; k < 4; k++) {
                int ee = e0 + k;
                int r = ee / IN_F;
                int c = ee - r * IN_F;
                float x = (k == 0) ? v.x : (k == 1) ? v.y : (k == 2) ? v.z : v.w;
                g_feat16[(size_t)r * K_PAD + c] = __float2half(x);
            }
        }
        return;
    }
    b -= PREP_FEAT_BLOCKS;

    if (b < PREP_W_BLOCKS) {
        // W transpose -> fp16; kblk = b % 45, nblk = b / 45
        __shared__ float tile[32][33];
        int k0 = (b % 45) * 32;
        int n0 = (b / 45) * 32;
        int tx = tid & 31, ty = tid >> 5;  // 32x8
        #pragma unroll
        for (int i = 0; i < 4; i++) {
            int k = k0 + ty + i * 8;
            tile[ty + i * 8][tx] = (k < IN_F) ? W[(size_t)k * OUT_F + n0 + tx] : 0.0f;
        }
        __syncthreads();
        #pragma unroll
        for (int i = 0; i < 4; i++) {
            int n = n0 + ty + i * 8;
            int k = k0 + tx;
            g_Wt[(size_t)n * K_PAD + k] = __float2half(tile[tx][ty + i * 8]);
        }
        return;
    }
    b -= PREP_W_BLOCKS;

    // bucket fill (per-block edge-width detect)
    {
        __shared__ int s_is64;
        if (tid == 0) {
            const int* e32 = (const int*)edges;
            int is64 = 1;
            for (int j = 0; j < 128; j++)
                if (e32[2 * j + 1] != 0) { is64 = 0; break; }
            s_is64 = is64;
        }
        __syncthreads();
        int e = b * 256 + tid;
        if (e >= N_EDGES) return;
        int dst, src;
        read_edge(edges, e, s_is64, dst, src);
        if (src < 0 || src >= N_NODES) return;
        if (dst < 0 || dst >= N_NODES) return;
        int slot = atomicAdd(&g_cnt[dst], 1);
        if (slot < CAP) g_srcs[(size_t)dst * CAP + slot] = src;
    }
}

// -------- launch 2: fused gather + noise + norm -> fp16 A (+ cnt reset) --------
// 192 threads; thread q owns 16B chunk q of the row (180 chunks = 1440 halfs)
#define GTH  192
#define NCHUNK 180

__global__ __launch_bounds__(GTH)
void gather_kernel(const float* __restrict__ noise) {
    int node = blockIdx.x;
    int cnt = g_cnt[node];
    if (cnt > CAP) cnt = CAP;
    const int* bucket = g_srcs + (size_t)node * CAP;
    int tid = threadIdx.x;
    bool active = (tid < NCHUNK);
    int c0 = tid * 8;  // first column of my 8-half chunk

    const float* __restrict__ nrow = noise + (size_t)node * IN_F;

    // accumulators: 8 floats (my chunk)
    float acc[8];
    #pragma unroll
    for (int k = 0; k < 8; k++) {
        int c = c0 + k;
        acc[k] = (active && c < IN_F) ? __ldg(nrow + c) : 0.0f;
    }

    const uint4* __restrict__ frow_base = (const uint4*)g_feat16;  // row stride 180 uint4
    int e = 0;
    for (; e + 2 <= cnt; e += 2) {
        int s0 = __ldg(bucket + e);
        int s1 = __ldg(bucket + e + 1);
        if (active) {
            uint4 u0 = __ldg(frow_base + (size_t)s0 * NCHUNK + tid);
            uint4 u1 = __ldg(frow_base + (size_t)s1 * NCHUNK + tid);
            const __half2* h0 = (const __half2*)&u0;
            const __half2* h1 = (const __half2*)&u1;
            #pragma unroll
            for (int p = 0; p < 4; p++) {
                float2 a = __half22float2(h0[p]);
                float2 c2 = __half22float2(h1[p]);
                acc[2 * p + 0] += a.x + c2.x;
                acc[2 * p + 1] += a.y + c2.y;
            }
        }
    }
    if (e < cnt && active) {
        int s0 = __ldg(bucket + e);
        uint4 u0 = __ldg(frow_base + (size_t)s0 * NCHUNK + tid);
        const __half2* h0 = (const __half2*)&u0;
        #pragma unroll
        for (int p = 0; p < 4; p++) {
            float2 a = __half22float2(h0[p]);
            acc[2 * p + 0] += a.x;
            acc[2 * p + 1] += a.y;
        }
    }

    float ss = 0.0f;
    #pragma unroll
    for (int k = 0; k < 8; k++) ss += acc[k] * acc[k];
    #pragma unroll
    for (int off = 16; off; off >>= 1)
        ss += __shfl_xor_sync(0xFFFFFFFFu, ss, off);
    __shared__ float sred[6];
    __shared__ float s_inv;
    int lane = tid & 31, w = tid >> 5;
    if (lane == 0) sred[w] = ss;
    __syncthreads();
    if (tid == 0) {
        float tot = 0.0f;
        #pragma unroll
        for (int i = 0; i < 6; i++) tot += sred[i];
        s_inv = 1.0f / fmaxf(sqrtf(tot), 1e-12f);
        g_cnt[node] = 0;   // reset for next replay
    }
    __syncthreads();
    float inv = s_inv;

    if (active) {
        uint4 outv;
        __half2* ho = (__half2*)&outv;
        #pragma unroll
        for (int p = 0; p < 4; p++)
            ho[p] = __floats2half2_rn(acc[2 * p] * inv, acc[2 * p + 1] * inv);
        ((uint4*)(g_A + (size_t)node * K_PAD))[tid] = outv;
    }
}

// -------- launch 3: GEMM fp16 mma, BM=128 BN=64 BK=32, 256 thr, 4-stage (R16, passing) --------
#define ROWB    80
#define A_SZ    10240
#define STGSZ   15360
#define SMEM_SZ 61440

__global__ __launch_bounds__(256, 3)
void gemm_mma_kernel(const float* __restrict__ bias, float* __restrict__ out) {
    extern __shared__ __align__(128) char smem[];
    uint32_t sb = smem_u32(smem);
    int tid = threadIdx.x;
    int lane = tid & 31, wid = tid >> 5;
    int warp_m = wid & 3;
    int warp_n = wid >> 2;
    int m0 = blockIdx.x * 128;
    int n0 = blockIdx.y * 64;

    float acc[2][4][4];
    #pragma unroll
    for (int t = 0; t < 2; t++)
        #pragma unroll
        for (int nt = 0; nt < 4; nt++)
            #pragma unroll
            for (int j = 0; j < 4; j++) acc[t][nt][j] = 0.0f;

    auto fill = [&](int stage, int k0) {
        uint32_t sbuf = sb + stage * STGSZ;
        #pragma unroll
        for (int i = 0; i < 3; i++) {
            int idx = tid + 256 * i;
            int isB = (idx >= 512);
            int cc = isB ? (idx - 512) : idx;
            int row = cc >> 2, kc = cc & 3;
            const __half* g = isB ? g_Wt : g_A;
            int rbase = isB ? n0 : m0;
            uint32_t dst = sbuf + (isB ? A_SZ : 0) + row * ROWB + kc * 16;
            cp16(dst, g + (size_t)(rbase + row) * K_PAD + k0 + kc * 8);
        }
    };

    fill(0, 0);
    cp_commit();
    fill(1, BK);
    cp_commit();
    fill(2, 2 * BK);
    cp_commit();

    uint32_t afr[2][2][4], bfr[2][2][4];
    int stage = 0;

    auto load_frags = [&](int buf, uint32_t bo, int kk) {
        #pragma unroll
        for (int t = 0; t < 2; t++) {
            uint32_t ro = (uint32_t)((warp_m * 32 + t * 16 + (lane & 15)) * ROWB
                                     + (kk + (lane >> 4) * 8) * 2);
            ldmx4(afr[buf][t], bo + ro);
        }
        #pragma unroll
        for (int u = 0; u < 2; u++) {
            uint32_t ro = (uint32_t)((warp_n * 32 + u * 16 + (lane & 15)) * ROWB
                                     + (kk + (lane >> 4) * 8) * 2);
            ldmx4(bfr[buf][u], bo + A_SZ + ro);
        }
    };
    auto do_mma = [&](int buf) {
        #pragma unroll
        for (int t = 0; t < 2; t++)
            #pragma unroll
            for (int u = 0; u < 2; u++)
                #pragma unroll
                for (int v = 0; v < 2; v++) {
                    int nt = u * 2 + v;
                    uint32_t bf[2] = { bfr[buf][u][v], bfr[buf][u][v + 2] };
                    mma_f16(acc[t][nt], afr[buf][t], bf);
                }
    };

    for (int kb = 0; kb < N_KT; kb++) {
        if (kb + 3 <= N_KT) cp_wait<2>();
        else if (kb + 2 == N_KT) cp_wait<1>();
        else cp_wait<0>();
        __syncthreads();

        if (kb + 3 < N_KT) {
            fill((stage + 3) & 3, (kb + 3) * BK);
            cp_commit();
        }

        uint32_t bo = sb + stage * STGSZ;
        load_frags(0, bo, 0);
        load_frags(1, bo, 16);
        do_mma(0);
        do_mma(1);
        __syncthreads();
        stage = (stage + 1) & 3;
    }

    #pragma unroll
    for (int t = 0; t < 2; t++) {
        int gm = m0 + warp_m * 32 + t * 16 + (lane >> 2);
        #pragma unroll
        for (int nt = 0; nt < 4; nt++) {
            int col = n0 + warp_n * 32 + nt * 8 + 2 * (lane & 3);
            float2 b2 = *(const float2*)(bias + col);
            float* c = acc[t][nt];
            if (gm < N_NODES)
                *(float2*)(out + (size_t)gm * OUT_F + col) =
                    make_float2(c[0] + b2.x, c[1] + b2.y);
            if (gm + 8 < N_NODES)
                *(float2*)(out + (size_t)(gm + 8) * OUT_F + col) =
                    make_float2(c[2] + b2.x, c[3] + b2.y);
        }
    }
}

extern "C" void kernel_launch(void* const* d_in, const int* in_sizes, int n_in,
                              void* d_out, int out_size) {
    const float* feat   = (const float*)d_in[0];
    const void*  edges  = d_in[1];
    const float* weight = (const float*)d_in[2];
    const float* bias   = (const float*)d_in[3];
    const float* noise  = (const float*)d_in[4];
    float*       out    = (float*)d_out;

    (void)in_sizes; (void)n_in; (void)out_size;

    cudaFuncSetAttribute(gemm_mma_kernel, cudaFuncAttributeMaxDynamicSharedMemorySize, SMEM_SZ);

    prep_kernel<<<PREP_GRID, 256>>>(feat, weight, edges);
    gather_kernel<<<N_NODES, GTH>>>(noise);
    gemm_mma_kernel<<<dim3(M_PADR / 128, OUT_F / 64), 256, SMEM_SZ>>>(bias, out);
}